// round 3
// baseline (speedup 1.0000x reference)
#include <cuda_runtime.h>
#include <math.h>

// Problem dims (fixed by reference setup_inputs)
#define BB 2048
#define KK 8
#define OO 256
#define II 512
#define TINY 1e-10f

// Scratch (no allocations allowed)
__device__ int d_kstar[BB];
__device__ int d_counts[KK];
__device__ int d_offsets[KK];
__device__ int d_order[BB];

// ---------------- prep kernels ----------------

__global__ void k_zero_counts() {
    if (threadIdx.x < KK) d_counts[threadIdx.x] = 0;
}

// per-batch argmax of (mix_weights[k] + gumbel(u)) / TAU, plus histogram
__global__ void k_select(const float* __restrict__ mixw,
                         const float* __restrict__ u) {
    int b = blockIdx.x * blockDim.x + threadIdx.x;
    if (b >= BB) return;
    float best = -1e30f;
    int bi = 0;
#pragma unroll
    for (int k = 0; k < KK; k++) {
        float uu = u[b * KK + k];
        float g = -logf(-logf(uu + TINY) + TINY);
        float sc = mixw[k] + g;          // TAU = 1
        if (sc > best) { best = sc; bi = k; }
    }
    d_kstar[b] = bi;
    atomicAdd(&d_counts[bi], 1);
}

__global__ void k_scan() {
    if (threadIdx.x == 0) {
        int acc = 0;
#pragma unroll
        for (int k = 0; k < KK; k++) {
            d_offsets[k] = acc;
            acc += d_counts[k];
        }
    }
}

__global__ void k_scatter() {
    int b = blockIdx.x * blockDim.x + threadIdx.x;
    if (b >= BB) return;
    int pos = atomicAdd(&d_offsets[d_kstar[b]], 1);
    d_order[pos] = b;
}

// ---------------- main kernel ----------------
// grid: (OO/8, BB/TB). 8 warps/block, warp w owns o = bx*8 + w.
// Each block handles TB sorted batches; X rows staged in shared;
// mean/exp(log_sigma) rows held in registers, reloaded only on k-change.

#define TB 16

__global__ __launch_bounds__(256)
void k_main(const float* __restrict__ X,
            const float* __restrict__ mean,
            const float* __restrict__ log_sigma,
            const float* __restrict__ eps,
            float* __restrict__ out) {
    __shared__ float Xs[TB][II];
    __shared__ int bs[TB];
    __shared__ int ks[TB];

    const int tid  = threadIdx.x;
    const int warp = tid >> 5;
    const int lane = tid & 31;
    const int o    = blockIdx.x * 8 + warp;
    const int j0   = blockIdx.y * TB;

    if (tid < TB) {
        int b = d_order[j0 + tid];
        bs[tid] = b;
        ks[tid] = d_kstar[b];
    }
    __syncthreads();

    // stage X rows: TB*II floats = TB*128 float4, 256 threads -> TB/2 each
#pragma unroll
    for (int v = tid; v < TB * (II / 4); v += 256) {
        int j = v / (II / 4);
        int i4 = v % (II / 4);
        float4 xv = reinterpret_cast<const float4*>(X + (size_t)bs[j] * II)[i4];
        reinterpret_cast<float4*>(&Xs[j][0])[i4] = xv;
    }
    __syncthreads();

    int curk = -1;
    float4 m[4], s[4];

#pragma unroll 1
    for (int j = 0; j < TB; j++) {
        const int b = bs[j];
        const int k = ks[j];
        if (k != curk) {               // uniform across warp
            curk = k;
            const float4* mp = reinterpret_cast<const float4*>(
                mean + ((size_t)(k * OO + o)) * II);
            const float4* lp = reinterpret_cast<const float4*>(
                log_sigma + ((size_t)(k * OO + o)) * II);
#pragma unroll
            for (int c = 0; c < 4; c++) {
                int idx = c * 32 + lane;       // float4 index within row
                m[c] = mp[idx];
                float4 l = lp[idx];
                s[c] = make_float4(expf(l.x), expf(l.y), expf(l.z), expf(l.w));
            }
        }

        const float4* ep = reinterpret_cast<const float4*>(
            eps + ((size_t)b * OO + o) * II);

        float acc = 0.0f;
#pragma unroll
        for (int c = 0; c < 4; c++) {
            int idx = c * 32 + lane;
            float4 e = ep[idx];
            float4 x = reinterpret_cast<const float4*>(&Xs[j][0])[idx];
            acc = fmaf(x.x, fmaf(s[c].x, e.x, m[c].x), acc);
            acc = fmaf(x.y, fmaf(s[c].y, e.y, m[c].y), acc);
            acc = fmaf(x.z, fmaf(s[c].z, e.z, m[c].z), acc);
            acc = fmaf(x.w, fmaf(s[c].w, e.w, m[c].w), acc);
        }
#pragma unroll
        for (int off = 16; off > 0; off >>= 1)
            acc += __shfl_xor_sync(0xFFFFFFFFu, acc, off);
        if (lane == 0)
            out[(size_t)b * OO + o] = acc;
    }
}

// ---------------- launch ----------------

extern "C" void kernel_launch(void* const* d_in, const int* in_sizes, int n_in,
                              void* d_out, int out_size) {
    (void)in_sizes; (void)n_in; (void)out_size;
    const float* X    = (const float*)d_in[0];
    const float* mixw = (const float*)d_in[1];
    const float* mean = (const float*)d_in[2];
    const float* lsig = (const float*)d_in[3];
    const float* u    = (const float*)d_in[4];
    const float* eps  = (const float*)d_in[5];
    float* out = (float*)d_out;

    k_zero_counts<<<1, 32>>>();
    k_select<<<BB / 256, 256>>>(mixw, u);
    k_scan<<<1, 32>>>();
    k_scatter<<<BB / 256, 256>>>();

    dim3 grid(OO / 8, BB / TB);
    k_main<<<grid, 256>>>(X, mean, lsig, eps, out);
}

// round 4
// speedup vs baseline: 1.2194x; 1.2194x over previous
#include <cuda_runtime.h>
#include <math.h>

// Problem dims (fixed by reference setup_inputs)
#define BB 2048
#define KK 8
#define OO 256
#define II 512
#define TINY 1e-10f

// Scratch (no allocations allowed). d_counts is zero at module load and is
// re-zeroed by k_scan_scatter at the end of every launch -> deterministic.
__device__ int d_kstar[BB];
__device__ int d_counts[KK];
__device__ int d_order[BB];

// ---------------- prep kernel 1: select + block-local histogram ----------------
// grid 8 x 256. One thread per batch. 64 global atomics total (8 blocks x 8 k).
__global__ void k_select_hist(const float* __restrict__ mixw,
                              const float* __restrict__ u) {
    __shared__ int hist[KK];
    int tid = threadIdx.x;
    if (tid < KK) hist[tid] = 0;
    __syncthreads();

    int b = blockIdx.x * blockDim.x + tid;
    float best = -1e30f;
    int bi = 0;
#pragma unroll
    for (int k = 0; k < KK; k++) {
        float uu = u[b * KK + k];
        float g = -logf(-logf(uu + TINY) + TINY);
        float sc = mixw[k] + g;          // TAU = 1
        if (sc > best) { best = sc; bi = k; }
    }
    d_kstar[b] = bi;
    atomicAdd(&hist[bi], 1);
    __syncthreads();
    if (tid < KK) atomicAdd(&d_counts[tid], hist[tid]);
}

// ---------------- prep kernel 2: scan + scatter (single block) ----------------
// Positions within a k-group may be any permutation (only clustering matters).
__global__ void k_scan_scatter() {
    __shared__ int soff[KK];
    int tid = threadIdx.x;
    if (tid == 0) {
        int acc = 0;
#pragma unroll
        for (int k = 0; k < KK; k++) {
            soff[k] = acc;
            acc += d_counts[k];
        }
    }
    __syncthreads();
#pragma unroll
    for (int b = tid; b < BB; b += 1024) {
        int pos = atomicAdd(&soff[d_kstar[b]], 1);   // smem atomic: fast
        d_order[pos] = b;
    }
    __syncthreads();
    if (tid < KK) d_counts[tid] = 0;                 // reset for next replay
}

// ---------------- main kernel ----------------
// grid: (OO/8, BB/TB). 8 warps/block, warp w owns o = bx*8 + w.
// Block handles TB sorted batches; X rows staged in shared; mean/exp(log_sigma)
// rows in registers, reloaded only on k-change (rare after sort).
// eps is software-pipelined: prefetch j+1 (streaming, __ldcs) before the
// FMA/shuffle tail of j, with 4 independent accumulator chains.

#define TB 16

__global__ __launch_bounds__(256)
void k_main(const float* __restrict__ X,
            const float* __restrict__ mean,
            const float* __restrict__ log_sigma,
            const float* __restrict__ eps,
            float* __restrict__ out) {
    __shared__ float Xs[TB][II];
    __shared__ int bs[TB];
    __shared__ int ks[TB];

    const int tid  = threadIdx.x;
    const int warp = tid >> 5;
    const int lane = tid & 31;
    const int o    = blockIdx.x * 8 + warp;
    const int j0   = blockIdx.y * TB;

    if (tid < TB) {
        int b = d_order[j0 + tid];
        bs[tid] = b;
        ks[tid] = d_kstar[b];
    }
    __syncthreads();

    // stage X rows: TB*II floats = TB*128 float4, 256 threads
#pragma unroll
    for (int v = tid; v < TB * (II / 4); v += 256) {
        int j = v / (II / 4);
        int i4 = v % (II / 4);
        float4 xv = reinterpret_cast<const float4*>(X + (size_t)bs[j] * II)[i4];
        reinterpret_cast<float4*>(&Xs[j][0])[i4] = xv;
    }
    __syncthreads();

    int curk = -1;
    float4 m[4], s[4];
    float4 e[4];

    // prime the pipeline: eps for j=0
    {
        const float4* ep0 = reinterpret_cast<const float4*>(
            eps + ((size_t)bs[0] * OO + o) * II);
#pragma unroll
        for (int c = 0; c < 4; c++) e[c] = __ldcs(ep0 + c * 32 + lane);
    }

#pragma unroll 1
    for (int j = 0; j < TB; j++) {
        // issue next iteration's eps loads FIRST (independent of everything below)
        float4 en[4];
        {
            const int jn = (j + 1 < TB) ? j + 1 : j;    // last iter: dummy reload
            const float4* epn = reinterpret_cast<const float4*>(
                eps + ((size_t)bs[jn] * OO + o) * II);
#pragma unroll
            for (int c = 0; c < 4; c++) en[c] = __ldcs(epn + c * 32 + lane);
        }

        const int k = ks[j];
        if (k != curk) {                 // uniform across warp; rare after sort
            curk = k;
            const float4* mp = reinterpret_cast<const float4*>(
                mean + ((size_t)(k * OO + o)) * II);
            const float4* lp = reinterpret_cast<const float4*>(
                log_sigma + ((size_t)(k * OO + o)) * II);
#pragma unroll
            for (int c = 0; c < 4; c++) {
                int idx = c * 32 + lane;
                m[c] = mp[idx];
                float4 l = lp[idx];
                s[c] = make_float4(expf(l.x), expf(l.y), expf(l.z), expf(l.w));
            }
        }

        // 4 independent accumulator chains
        float a0 = 0.0f, a1 = 0.0f, a2 = 0.0f, a3 = 0.0f;
        const float4* xp = reinterpret_cast<const float4*>(&Xs[j][0]);
        {
            float4 x = xp[0 * 32 + lane];
            a0 = fmaf(x.x, fmaf(s[0].x, e[0].x, m[0].x), a0);
            a0 = fmaf(x.y, fmaf(s[0].y, e[0].y, m[0].y), a0);
            a0 = fmaf(x.z, fmaf(s[0].z, e[0].z, m[0].z), a0);
            a0 = fmaf(x.w, fmaf(s[0].w, e[0].w, m[0].w), a0);
        }
        {
            float4 x = xp[1 * 32 + lane];
            a1 = fmaf(x.x, fmaf(s[1].x, e[1].x, m[1].x), a1);
            a1 = fmaf(x.y, fmaf(s[1].y, e[1].y, m[1].y), a1);
            a1 = fmaf(x.z, fmaf(s[1].z, e[1].z, m[1].z), a1);
            a1 = fmaf(x.w, fmaf(s[1].w, e[1].w, m[1].w), a1);
        }
        {
            float4 x = xp[2 * 32 + lane];
            a2 = fmaf(x.x, fmaf(s[2].x, e[2].x, m[2].x), a2);
            a2 = fmaf(x.y, fmaf(s[2].y, e[2].y, m[2].y), a2);
            a2 = fmaf(x.z, fmaf(s[2].z, e[2].z, m[2].z), a2);
            a2 = fmaf(x.w, fmaf(s[2].w, e[2].w, m[2].w), a2);
        }
        {
            float4 x = xp[3 * 32 + lane];
            a3 = fmaf(x.x, fmaf(s[3].x, e[3].x, m[3].x), a3);
            a3 = fmaf(x.y, fmaf(s[3].y, e[3].y, m[3].y), a3);
            a3 = fmaf(x.z, fmaf(s[3].z, e[3].z, m[3].z), a3);
            a3 = fmaf(x.w, fmaf(s[3].w, e[3].w, m[3].w), a3);
        }
        float acc = (a0 + a1) + (a2 + a3);

#pragma unroll
        for (int off = 16; off > 0; off >>= 1)
            acc += __shfl_xor_sync(0xFFFFFFFFu, acc, off);
        if (lane == 0)
            out[(size_t)bs[j] * OO + o] = acc;

        // rotate pipeline registers
#pragma unroll
        for (int c = 0; c < 4; c++) e[c] = en[c];
    }
}

// ---------------- launch ----------------

extern "C" void kernel_launch(void* const* d_in, const int* in_sizes, int n_in,
                              void* d_out, int out_size) {
    (void)in_sizes; (void)n_in; (void)out_size;
    const float* X    = (const float*)d_in[0];
    const float* mixw = (const float*)d_in[1];
    const float* mean = (const float*)d_in[2];
    const float* lsig = (const float*)d_in[3];
    const float* u    = (const float*)d_in[4];
    const float* eps  = (const float*)d_in[5];
    float* out = (float*)d_out;

    k_select_hist<<<BB / 256, 256>>>(mixw, u);
    k_scan_scatter<<<1, 1024>>>();

    dim3 grid(OO / 8, BB / TB);
    k_main<<<grid, 256>>>(X, mean, lsig, eps, out);
}

// round 5
// speedup vs baseline: 1.2584x; 1.0320x over previous
#include <cuda_runtime.h>
#include <math.h>

// Problem dims (fixed by reference setup_inputs)
#define BB 2048
#define KK 8
#define OO 256
#define II 512
#define TINY 1e-10f

// Scratch (no allocations allowed)
__device__ int d_kstar[BB];
__device__ int d_order[BB];

// ---------------- prep: select + hist + scan + scatter, ONE block ----------------
// 1024 threads, each owns batches t and t+1024. Scatter uses register-held
// kstar values; positions within a k-group are an arbitrary permutation
// (only the clustering matters) and the output is order-independent.
__global__ void k_prep(const float* __restrict__ mixw,
                       const float* __restrict__ u) {
    __shared__ int hist[KK];
    __shared__ int soff[KK];
    __shared__ float w[KK];
    const int t = threadIdx.x;
    if (t < KK) { hist[t] = 0; w[t] = mixw[t]; }
    __syncthreads();

    int kst[2];
#pragma unroll
    for (int r = 0; r < 2; r++) {
        const int b = t + r * 1024;
        float4 u0 = reinterpret_cast<const float4*>(u + b * KK)[0];
        float4 u1 = reinterpret_cast<const float4*>(u + b * KK)[1];
        float uu[KK] = {u0.x, u0.y, u0.z, u0.w, u1.x, u1.y, u1.z, u1.w};
        float best = -1e30f;
        int bi = 0;
#pragma unroll
        for (int k = 0; k < KK; k++) {
            float g = -logf(-logf(uu[k] + TINY) + TINY);
            float sc = w[k] + g;           // TAU = 1
            if (sc > best) { best = sc; bi = k; }
        }
        kst[r] = bi;
        d_kstar[b] = bi;
        atomicAdd(&hist[bi], 1);
    }
    __syncthreads();
    if (t == 0) {
        int acc = 0;
#pragma unroll
        for (int k = 0; k < KK; k++) { soff[k] = acc; acc += hist[k]; }
    }
    __syncthreads();
#pragma unroll
    for (int r = 0; r < 2; r++) {
        int pos = atomicAdd(&soff[kst[r]], 1);
        d_order[pos] = t + r * 1024;
    }
}

// ---------------- main kernel ----------------
// grid: (OO/8, BB/TB). 8 warps/block, warp w owns o = bx*8 + w.
// Block handles TB sorted batches; X rows staged in shared; mean/exp(log_sigma)
// in registers, reloaded only on k-change (rare after sort).
// eps software-pipelined with prefetch DISTANCE 2 using only 2 buffers:
// compute batch j from buffer p, then re-issue p with the load for j+2.
// Steady state: ~8 LDG.128 in flight per warp; 2 blocks/SM -> 16 KB/SM in
// flight, above the ~12 KB needed to saturate HBM.

#define TB 16

__global__ __launch_bounds__(256, 2)
void k_main(const float* __restrict__ X,
            const float* __restrict__ mean,
            const float* __restrict__ log_sigma,
            const float* __restrict__ eps,
            float* __restrict__ out) {
    __shared__ float Xs[TB][II];
    __shared__ int bs[TB];
    __shared__ int ks[TB];

    const int tid  = threadIdx.x;
    const int warp = tid >> 5;
    const int lane = tid & 31;
    const int o    = blockIdx.x * 8 + warp;
    const int j0   = blockIdx.y * TB;

    if (tid < TB) {
        int b = d_order[j0 + tid];
        bs[tid] = b;
        ks[tid] = d_kstar[b];
    }
    __syncthreads();

    // stage X rows: TB*II floats = TB*128 float4, 256 threads
#pragma unroll
    for (int v = tid; v < TB * (II / 4); v += 256) {
        int j = v / (II / 4);
        int i4 = v % (II / 4);
        float4 xv = reinterpret_cast<const float4*>(X + (size_t)bs[j] * II)[i4];
        reinterpret_cast<float4*>(&Xs[j][0])[i4] = xv;
    }
    __syncthreads();

    int curk = -1;
    float4 m[4], s[4];
    float4 e0[4], e1[4];

    auto load_eps = [&](float4* dst, int j) {
        const float4* ep = reinterpret_cast<const float4*>(
            eps + ((size_t)bs[j] * OO + o) * II);
#pragma unroll
        for (int c = 0; c < 4; c++) dst[c] = __ldcs(ep + c * 32 + lane);
    };

    auto reload_k = [&](int k) {
        if (k != curk) {               // uniform across warp; rare after sort
            curk = k;
            const float4* mp = reinterpret_cast<const float4*>(
                mean + ((size_t)(k * OO + o)) * II);
            const float4* lp = reinterpret_cast<const float4*>(
                log_sigma + ((size_t)(k * OO + o)) * II);
#pragma unroll
            for (int c = 0; c < 4; c++) {
                int idx = c * 32 + lane;
                m[c] = mp[idx];
                float4 l = lp[idx];
                s[c] = make_float4(expf(l.x), expf(l.y), expf(l.z), expf(l.w));
            }
        }
    };

    auto compute = [&](const float4* e, int j) -> float {
        const float4* xp = reinterpret_cast<const float4*>(&Xs[j][0]);
        float a0 = 0.f, a1 = 0.f, a2 = 0.f, a3 = 0.f;
        {
            float4 x = xp[0 * 32 + lane];
            a0 = fmaf(x.x, fmaf(s[0].x, e[0].x, m[0].x), a0);
            a0 = fmaf(x.y, fmaf(s[0].y, e[0].y, m[0].y), a0);
            a0 = fmaf(x.z, fmaf(s[0].z, e[0].z, m[0].z), a0);
            a0 = fmaf(x.w, fmaf(s[0].w, e[0].w, m[0].w), a0);
        }
        {
            float4 x = xp[1 * 32 + lane];
            a1 = fmaf(x.x, fmaf(s[1].x, e[1].x, m[1].x), a1);
            a1 = fmaf(x.y, fmaf(s[1].y, e[1].y, m[1].y), a1);
            a1 = fmaf(x.z, fmaf(s[1].z, e[1].z, m[1].z), a1);
            a1 = fmaf(x.w, fmaf(s[1].w, e[1].w, m[1].w), a1);
        }
        {
            float4 x = xp[2 * 32 + lane];
            a2 = fmaf(x.x, fmaf(s[2].x, e[2].x, m[2].x), a2);
            a2 = fmaf(x.y, fmaf(s[2].y, e[2].y, m[2].y), a2);
            a2 = fmaf(x.z, fmaf(s[2].z, e[2].z, m[2].z), a2);
            a2 = fmaf(x.w, fmaf(s[2].w, e[2].w, m[2].w), a2);
        }
        {
            float4 x = xp[3 * 32 + lane];
            a3 = fmaf(x.x, fmaf(s[3].x, e[3].x, m[3].x), a3);
            a3 = fmaf(x.y, fmaf(s[3].y, e[3].y, m[3].y), a3);
            a3 = fmaf(x.z, fmaf(s[3].z, e[3].z, m[3].z), a3);
            a3 = fmaf(x.w, fmaf(s[3].w, e[3].w, m[3].w), a3);
        }
        return (a0 + a1) + (a2 + a3);
    };

    auto finish = [&](float acc, int j) {
#pragma unroll
        for (int off = 16; off > 0; off >>= 1)
            acc += __shfl_xor_sync(0xFFFFFFFFu, acc, off);
        if (lane == 0)
            out[(size_t)bs[j] * OO + o] = acc;
    };

    // prime: batches 0 and 1 (8 loads in flight before loop)
    load_eps(e0, 0);
    load_eps(e1, 1);

#pragma unroll 1
    for (int j = 0; j < TB; j += 2) {
        // batch j from e0
        reload_k(ks[j]);
        float accA = compute(e0, j);
        {   // re-issue e0 with batch j+2 (WAR: after all e0 reads above)
            int jn = (j + 2 < TB) ? j + 2 : TB - 1;
            load_eps(e0, jn);
        }
        finish(accA, j);

        // batch j+1 from e1
        reload_k(ks[j + 1]);
        float accB = compute(e1, j + 1);
        {
            int jn = (j + 3 < TB) ? j + 3 : TB - 1;
            load_eps(e1, jn);
        }
        finish(accB, j + 1);
    }
}

// ---------------- launch ----------------

extern "C" void kernel_launch(void* const* d_in, const int* in_sizes, int n_in,
                              void* d_out, int out_size) {
    (void)in_sizes; (void)n_in; (void)out_size;
    const float* X    = (const float*)d_in[0];
    const float* mixw = (const float*)d_in[1];
    const float* mean = (const float*)d_in[2];
    const float* lsig = (const float*)d_in[3];
    const float* u    = (const float*)d_in[4];
    const float* eps  = (const float*)d_in[5];
    float* out = (float*)d_out;

    k_prep<<<1, 1024>>>(mixw, u);

    dim3 grid(OO / 8, BB / TB);
    k_main<<<grid, 256>>>(X, mean, lsig, eps, out);
}

// round 8
// speedup vs baseline: 1.4563x; 1.1573x over previous
#include <cuda_runtime.h>
#include <math.h>

// Problem dims (fixed by reference setup_inputs)
#define BB 2048
#define KK 8
#define OO 256
#define II 512
#define TINY 1e-10f

// Scratch (no allocations allowed)
__device__ int d_kstar[BB];
__device__ int d_order[BB];

// ---------------- prep: select + hist + scan + scatter, ONE block ----------------
__global__ void k_prep(const float* __restrict__ mixw,
                       const float* __restrict__ u) {
    __shared__ int hist[KK];
    __shared__ int soff[KK];
    __shared__ float w[KK];
    const int t = threadIdx.x;
    if (t < KK) { hist[t] = 0; w[t] = mixw[t]; }
    __syncthreads();

    int kst[2];
#pragma unroll
    for (int r = 0; r < 2; r++) {
        const int b = t + r * 1024;
        float4 u0 = reinterpret_cast<const float4*>(u + b * KK)[0];
        float4 u1 = reinterpret_cast<const float4*>(u + b * KK)[1];
        float uu[KK] = {u0.x, u0.y, u0.z, u0.w, u1.x, u1.y, u1.z, u1.w};
        float best = -1e30f;
        int bi = 0;
#pragma unroll
        for (int k = 0; k < KK; k++) {
            float g = -logf(-logf(uu[k] + TINY) + TINY);
            float sc = w[k] + g;           // TAU = 1
            if (sc > best) { best = sc; bi = k; }
        }
        kst[r] = bi;
        d_kstar[b] = bi;
        atomicAdd(&hist[bi], 1);
    }
    __syncthreads();
    if (t == 0) {
        int acc = 0;
#pragma unroll
        for (int k = 0; k < KK; k++) { soff[k] = acc; acc += hist[k]; }
    }
    __syncthreads();
#pragma unroll
    for (int r = 0; r < 2; r++) {
        int pos = atomicAdd(&soff[kst[r]], 1);
        d_order[pos] = t + r * 1024;
    }
}

// ---------------- cp.async helpers ----------------
__device__ __forceinline__ void cp16(void* smem_dst, const void* gsrc) {
    unsigned s = (unsigned)__cvta_generic_to_shared(smem_dst);
    asm volatile("cp.async.cg.shared.global [%0], [%1], 16;" :: "r"(s), "l"(gsrc));
}
#define CP_COMMIT() asm volatile("cp.async.commit_group;" ::: "memory")
#define CP_WAIT(n)  asm volatile("cp.async.wait_group %0;" :: "n"(n) : "memory")

// ---------------- main kernel ----------------
// grid: (OO/8, BB/TB). 8 warps/block, warp w owns o = bx*8 + w.
// Per batch j the block needs eps rows (b, o0..o0+7, :) = ONE contiguous 16KB
// tile. These are staged through a 4-stage cp.async smem pipeline, so
// DRAM-in-flight bytes (3 stages x 16KB x 2 blocks = 96KB/SM) are decoupled
// from registers and from the FMA/shuffle serial chain. X tile also staged
// via cp.async. mean/exp(log_sigma) live in registers, reloaded on k-change
// only (rare after the k-sort).

#define TB 16
#define STAGES 4

__global__ __launch_bounds__(256, 2)
void k_main(const float* __restrict__ X,
            const float* __restrict__ mean,
            const float* __restrict__ log_sigma,
            const float* __restrict__ eps,
            float* __restrict__ out) {
    __shared__ float Xs[TB][II];                 // 32 KB
    __shared__ float es[STAGES][8 * II];         // 64 KB
    __shared__ int bs[TB];
    __shared__ int ks[TB];

    const int tid  = threadIdx.x;
    const int warp = tid >> 5;
    const int lane = tid & 31;
    const int o    = blockIdx.x * 8 + warp;
    const int o0   = blockIdx.x * 8;
    const int j0   = blockIdx.y * TB;

    if (tid < TB) {
        int b = d_order[j0 + tid];
        bs[tid] = b;
        ks[tid] = d_kstar[b];
    }
    __syncthreads();

    // issue one 16KB eps tile (batch j) into stage slot
    auto issue_eps = [&](int slot, int j) {
        const float* base = eps + ((size_t)bs[j] * OO + o0) * II;
        float* dst = &es[slot][0];
#pragma unroll
        for (int r = 0; r < 4; r++) {
            int f = tid + r * 256;               // float4 index in 4096-float tile
            cp16(dst + f * 4, base + f * 4);
        }
    };

    // prologue: group 0 = X tile + eps stage 0; groups 1..S-2 = eps stages
    {
#pragma unroll
        for (int v = tid; v < TB * (II / 4); v += 256) {
            int row = v / (II / 4);
            int i4  = v % (II / 4);
            cp16(&Xs[row][i4 * 4], X + (size_t)bs[row] * II + i4 * 4);
        }
        issue_eps(0, 0);
        CP_COMMIT();
#pragma unroll
        for (int st = 1; st <= STAGES - 2; st++) {
            issue_eps(st, st);
            CP_COMMIT();
        }
    }

    int curk = -1;
    float4 m[4], s[4];

#pragma unroll 1
    for (int j = 0; j < TB; j++) {
        CP_WAIT(STAGES - 2);      // group j (and X on j=0) complete for this thread
        __syncthreads();          // visible to all warps; also WAR-protects reissue

        // issue batch j+S-1 into slot (j-1)%S (fully consumed at iter j-1)
        if (j + STAGES - 1 < TB)
            issue_eps((j + STAGES - 1) % STAGES, j + STAGES - 1);
        CP_COMMIT();              // uniform one-commit-per-iter accounting

        const int k = ks[j];
        if (k != curk) {          // uniform across warp; rare after sort
            curk = k;
            const float4* mp = reinterpret_cast<const float4*>(
                mean + ((size_t)(k * OO + o)) * II);
            const float4* lp = reinterpret_cast<const float4*>(
                log_sigma + ((size_t)(k * OO + o)) * II);
#pragma unroll
            for (int c = 0; c < 4; c++) {
                int idx = c * 32 + lane;
                m[c] = mp[idx];
                float4 l = lp[idx];
                s[c] = make_float4(expf(l.x), expf(l.y), expf(l.z), expf(l.w));
            }
        }

        const float4* ep = reinterpret_cast<const float4*>(&es[j % STAGES][warp * II]);
        const float4* xp = reinterpret_cast<const float4*>(&Xs[j][0]);

        float a0 = 0.f, a1 = 0.f, a2 = 0.f, a3 = 0.f;
        {
            float4 e = ep[0 * 32 + lane];
            float4 x = xp[0 * 32 + lane];
            a0 = fmaf(x.x, fmaf(s[0].x, e.x, m[0].x), a0);
            a0 = fmaf(x.y, fmaf(s[0].y, e.y, m[0].y), a0);
            a0 = fmaf(x.z, fmaf(s[0].z, e.z, m[0].z), a0);
            a0 = fmaf(x.w, fmaf(s[0].w, e.w, m[0].w), a0);
        }
        {
            float4 e = ep[1 * 32 + lane];
            float4 x = xp[1 * 32 + lane];
            a1 = fmaf(x.x, fmaf(s[1].x, e.x, m[1].x), a1);
            a1 = fmaf(x.y, fmaf(s[1].y, e.y, m[1].y), a1);
            a1 = fmaf(x.z, fmaf(s[1].z, e.z, m[1].z), a1);
            a1 = fmaf(x.w, fmaf(s[1].w, e.w, m[1].w), a1);
        }
        {
            float4 e = ep[2 * 32 + lane];
            float4 x = xp[2 * 32 + lane];
            a2 = fmaf(x.x, fmaf(s[2].x, e.x, m[2].x), a2);
            a2 = fmaf(x.y, fmaf(s[2].y, e.y, m[2].y), a2);
            a2 = fmaf(x.z, fmaf(s[2].z, e.z, m[2].z), a2);
            a2 = fmaf(x.w, fmaf(s[2].w, e.w, m[2].w), a2);
        }
        {
            float4 e = ep[3 * 32 + lane];
            float4 x = xp[3 * 32 + lane];
            a3 = fmaf(x.x, fmaf(s[3].x, e.x, m[3].x), a3);
            a3 = fmaf(x.y, fmaf(s[3].y, e.y, m[3].y), a3);
            a3 = fmaf(x.z, fmaf(s[3].z, e.z, m[3].z), a3);
            a3 = fmaf(x.w, fmaf(s[3].w, e.w, m[3].w), a3);
        }
        float acc = (a0 + a1) + (a2 + a3);

#pragma unroll
        for (int off = 16; off > 0; off >>= 1)
            acc += __shfl_xor_sync(0xFFFFFFFFu, acc, off);
        if (lane == 0)
            out[(size_t)bs[j] * OO + o] = acc;
    }
}

// ---------------- launch ----------------

extern "C" void kernel_launch(void* const* d_in, const int* in_sizes, int n_in,
                              void* d_out, int out_size) {
    (void)in_sizes; (void)n_in; (void)out_size;
    const float* X    = (const float*)d_in[0];
    const float* mixw = (const float*)d_in[1];
    const float* mean = (const float*)d_in[2];
    const float* lsig = (const float*)d_in[3];
    const float* u    = (const float*)d_in[4];
    const float* eps  = (const float*)d_in[5];
    float* out = (float*)d_out;

    k_prep<<<1, 1024>>>(mixw, u);

    dim3 grid(OO / 8, BB / TB);
    k_main<<<grid, 256>>>(X, mean, lsig, eps, out);
}

// round 9
// speedup vs baseline: 1.4736x; 1.0119x over previous
#include <cuda_runtime.h>
#include <math.h>

// Problem dims (fixed by reference setup_inputs)
#define BB 2048
#define KK 8
#define OO 256
#define II 512
#define TINY 1e-10f

// Scratch (no allocations allowed)
__device__ int d_kstar[BB];
__device__ int d_order[BB];

// ---------------- prep: select + hist + scan + scatter, ONE block ----------------
__global__ void k_prep(const float* __restrict__ mixw,
                       const float* __restrict__ u) {
    __shared__ int hist[KK];
    __shared__ int soff[KK];
    __shared__ float w[KK];
    const int t = threadIdx.x;
    if (t < KK) { hist[t] = 0; w[t] = mixw[t]; }
    __syncthreads();

    int kst[2];
#pragma unroll
    for (int r = 0; r < 2; r++) {
        const int b = t + r * 1024;
        float4 u0 = reinterpret_cast<const float4*>(u + b * KK)[0];
        float4 u1 = reinterpret_cast<const float4*>(u + b * KK)[1];
        float uu[KK] = {u0.x, u0.y, u0.z, u0.w, u1.x, u1.y, u1.z, u1.w};
        float best = -1e30f;
        int bi = 0;
#pragma unroll
        for (int k = 0; k < KK; k++) {
            float g = -logf(-logf(uu[k] + TINY) + TINY);
            float sc = w[k] + g;           // TAU = 1
            if (sc > best) { best = sc; bi = k; }
        }
        kst[r] = bi;
        d_kstar[b] = bi;
        atomicAdd(&hist[bi], 1);
    }
    __syncthreads();
    if (t == 0) {
        int acc = 0;
#pragma unroll
        for (int k = 0; k < KK; k++) { soff[k] = acc; acc += hist[k]; }
    }
    __syncthreads();
#pragma unroll
    for (int r = 0; r < 2; r++) {
        int pos = atomicAdd(&soff[kst[r]], 1);
        d_order[pos] = t + r * 1024;
    }
}

// ---------------- cp.async helpers ----------------
__device__ __forceinline__ void cp16(void* smem_dst, const void* gsrc) {
    unsigned s = (unsigned)__cvta_generic_to_shared(smem_dst);
    asm volatile("cp.async.cg.shared.global [%0], [%1], 16;" :: "r"(s), "l"(gsrc));
}
#define CP_COMMIT() asm volatile("cp.async.commit_group;" ::: "memory")
#define CP_WAIT(n)  asm volatile("cp.async.wait_group %0;" :: "n"(n) : "memory")

// ---------------- main kernel ----------------
// grid: (OO/8, BB/TB). 8 warps/block, warp w owns o = bx*8 + w.
// WARP-LOCAL eps pipeline: warp w stages ONLY its own 2KB row slice
// (b, o, :) into es[slot][w*II], with lane l copying exactly the float4s
// c*32+l it later reads. No cross-thread hazards -> ZERO barriers in the
// steady-state loop; ordering is purely per-thread cp.async.wait_group.
// Warps free-run: one warp's k-reload/shuffle tail no longer stalls the
// other warps' DRAM issue. X tile staged once (single __syncthreads).
// mean/exp(log_sigma) in registers, reloaded only on k-change (rare after
// the k-sort in prep).

#define TB 16
#define STAGES 4

__global__ __launch_bounds__(256, 2)
void k_main(const float* __restrict__ X,
            const float* __restrict__ mean,
            const float* __restrict__ log_sigma,
            const float* __restrict__ eps,
            float* __restrict__ out) {
    __shared__ float Xs[TB][II];                 // 32 KB
    __shared__ float es[STAGES][8 * II];         // 64 KB
    __shared__ int bs[TB];
    __shared__ int ks[TB];

    const int tid  = threadIdx.x;
    const int warp = tid >> 5;
    const int lane = tid & 31;
    const int o    = blockIdx.x * 8 + warp;
    const int j0   = blockIdx.y * TB;

    if (tid < TB) {
        int b = d_order[j0 + tid];
        bs[tid] = b;
        ks[tid] = d_kstar[b];
    }
    __syncthreads();            // bs/ks visible before any issue

    // warp-local: stage eps row (bs[j], o, :) into es[slot][warp*II]
    auto issue_eps = [&](int slot, int j) {
        const float* base = eps + ((size_t)bs[j] * OO + o) * II;
        float* dst = &es[slot][warp * II];
#pragma unroll
        for (int c = 0; c < 4; c++) {
            int f = c * 32 + lane;              // matches read pattern exactly
            cp16(dst + f * 4, base + f * 4);
        }
    };

    // prologue: group0 = X tile + eps stage 0; then stages 1..S-2
    {
#pragma unroll
        for (int v = tid; v < TB * (II / 4); v += 256) {
            int row = v / (II / 4);
            int i4  = v % (II / 4);
            cp16(&Xs[row][i4 * 4], X + (size_t)bs[row] * II + i4 * 4);
        }
        issue_eps(0, 0);
        CP_COMMIT();
#pragma unroll
        for (int st = 1; st <= STAGES - 2; st++) {
            issue_eps(st, st);
            CP_COMMIT();
        }
        CP_WAIT(STAGES - 2);    // group 0 (X + stage 0) complete
        __syncthreads();        // publish X to all warps (one-time)
    }

    int curk = -1;
    float4 m[4], s[4];

#pragma unroll 1
    for (int j = 0; j < TB; j++) {
        CP_WAIT(STAGES - 2);    // per-thread: guarantees group j complete

        // issue batch j+S-1 into slot (j-1)%S (this warp consumed it at j-1;
        // same-thread same-address ordering makes the WAR safe)
        if (j + STAGES - 1 < TB)
            issue_eps((j + STAGES - 1) % STAGES, j + STAGES - 1);
        CP_COMMIT();            // uniform one-commit-per-iter accounting

        const int k = ks[j];
        if (k != curk) {        // uniform across warp; rare after sort
            curk = k;
            const float4* mp = reinterpret_cast<const float4*>(
                mean + ((size_t)(k * OO + o)) * II);
            const float4* lp = reinterpret_cast<const float4*>(
                log_sigma + ((size_t)(k * OO + o)) * II);
#pragma unroll
            for (int c = 0; c < 4; c++) {
                int idx = c * 32 + lane;
                m[c] = mp[idx];
                float4 l = lp[idx];
                s[c] = make_float4(expf(l.x), expf(l.y), expf(l.z), expf(l.w));
            }
        }

        const float4* ep = reinterpret_cast<const float4*>(&es[j % STAGES][warp * II]);
        const float4* xp = reinterpret_cast<const float4*>(&Xs[j][0]);

        float a0 = 0.f, a1 = 0.f, a2 = 0.f, a3 = 0.f;
        {
            float4 e = ep[0 * 32 + lane];
            float4 x = xp[0 * 32 + lane];
            a0 = fmaf(x.x, fmaf(s[0].x, e.x, m[0].x), a0);
            a0 = fmaf(x.y, fmaf(s[0].y, e.y, m[0].y), a0);
            a0 = fmaf(x.z, fmaf(s[0].z, e.z, m[0].z), a0);
            a0 = fmaf(x.w, fmaf(s[0].w, e.w, m[0].w), a0);
        }
        {
            float4 e = ep[1 * 32 + lane];
            float4 x = xp[1 * 32 + lane];
            a1 = fmaf(x.x, fmaf(s[1].x, e.x, m[1].x), a1);
            a1 = fmaf(x.y, fmaf(s[1].y, e.y, m[1].y), a1);
            a1 = fmaf(x.z, fmaf(s[1].z, e.z, m[1].z), a1);
            a1 = fmaf(x.w, fmaf(s[1].w, e.w, m[1].w), a1);
        }
        {
            float4 e = ep[2 * 32 + lane];
            float4 x = xp[2 * 32 + lane];
            a2 = fmaf(x.x, fmaf(s[2].x, e.x, m[2].x), a2);
            a2 = fmaf(x.y, fmaf(s[2].y, e.y, m[2].y), a2);
            a2 = fmaf(x.z, fmaf(s[2].z, e.z, m[2].z), a2);
            a2 = fmaf(x.w, fmaf(s[2].w, e.w, m[2].w), a2);
        }
        {
            float4 e = ep[3 * 32 + lane];
            float4 x = xp[3 * 32 + lane];
            a3 = fmaf(x.x, fmaf(s[3].x, e.x, m[3].x), a3);
            a3 = fmaf(x.y, fmaf(s[3].y, e.y, m[3].y), a3);
            a3 = fmaf(x.z, fmaf(s[3].z, e.z, m[3].z), a3);
            a3 = fmaf(x.w, fmaf(s[3].w, e.w, m[3].w), a3);
        }
        float acc = (a0 + a1) + (a2 + a3);

#pragma unroll
        for (int off = 16; off > 0; off >>= 1)
            acc += __shfl_xor_sync(0xFFFFFFFFu, acc, off);
        if (lane == 0)
            out[(size_t)bs[j] * OO + o] = acc;
    }
}

// ---------------- launch ----------------

extern "C" void kernel_launch(void* const* d_in, const int* in_sizes, int n_in,
                              void* d_out, int out_size) {
    (void)in_sizes; (void)n_in; (void)out_size;
    const float* X    = (const float*)d_in[0];
    const float* mixw = (const float*)d_in[1];
    const float* mean = (const float*)d_in[2];
    const float* lsig = (const float*)d_in[3];
    const float* u    = (const float*)d_in[4];
    const float* eps  = (const float*)d_in[5];
    float* out = (float*)d_out;

    k_prep<<<1, 1024>>>(mixw, u);

    dim3 grid(OO / 8, BB / TB);
    k_main<<<grid, 256>>>(X, mean, lsig, eps, out);
}